// round 6
// baseline (speedup 1.0000x reference)
#include <cuda_runtime.h>
#include <math.h>
#include <stdint.h>

// Problem constants
#define B_   2
#define TX_  1024
#define TY_  4096
#define C_   768
#define H_   12
#define D_   64

// Scratch (device globals: no allocation allowed)
__device__ float g_q[B_ * TX_ * C_];
__device__ float g_k[B_ * TY_ * C_];
__device__ float g_v[B_ * TY_ * C_];
__device__ float g_o[B_ * TX_ * C_];

__device__ __forceinline__ float to_tf32(float x) {
    float r;
    asm("cvt.rna.tf32.f32 %0, %1;" : "=f"(r) : "f"(x));
    return r;
}

// mma.sync m16n8k8 tf32 (sm_80+, valid on base sm_103 target -> HMMA)
__device__ __forceinline__ void mma_tf32(float* d, const uint32_t* a, const uint32_t* b) {
    asm volatile(
        "mma.sync.aligned.m16n8k8.row.col.f32.tf32.tf32.f32 "
        "{%0,%1,%2,%3}, {%4,%5,%6,%7}, {%8,%9}, {%0,%1,%2,%3};"
        : "+f"(d[0]), "+f"(d[1]), "+f"(d[2]), "+f"(d[3])
        : "r"(a[0]), "r"(a[1]), "r"(a[2]), "r"(a[3]), "r"(b[0]), "r"(b[1]));
}

// ---------------------------------------------------------------------------
// Tensor-core tf32 GEMM with 3xTF32 compensation.
// out = A[M,K] @ W[K,N], fp32 in/out. Block tile 128x128, 256 threads,
// 8 warps (4x2), warp tile 32x64 = 2x8 m16n8k8 fragments. K-chunk = 16.
// If out1 != nullptr: cols [0,splitN) -> out0, [splitN,N) -> out1
// (block spans 128 cols; splitN is a multiple of 128 so no intra-block split).
// ---------------------------------------------------------------------------
#define PADW 132

__global__ __launch_bounds__(256, 1) void gemm_tc(
    const float* __restrict__ A, const float* __restrict__ W,
    float* __restrict__ out0, float* __restrict__ out1,
    int N, int K, int splitN)
{
    __shared__ float Ash[16][PADW];  // [k][m] hi
    __shared__ float Asl[16][PADW];  // [k][m] lo
    __shared__ float Bsh[16][PADW];  // [k][n] hi
    __shared__ float Bsl[16][PADW];  // [k][n] lo

    const int tid = threadIdx.x;
    const int wid = tid >> 5, lane = tid & 31;
    const int g = lane >> 2, t = lane & 3;
    const int warp_m = (wid >> 1) * 32;     // 0,32,64,96
    const int warp_n = (wid & 1) * 64;      // 0,64
    const int bn = blockIdx.x * 128, bm = blockIdx.y * 128;

    float acc[2][8][4];
#pragma unroll
    for (int mt = 0; mt < 2; mt++)
#pragma unroll
        for (int nt = 0; nt < 8; nt++)
#pragma unroll
            for (int e = 0; e < 4; e++) acc[mt][nt][e] = 0.f;

    const int nch = K / 16;
    for (int c = 0; c < nch; c++) {
        const int k0 = c * 16;
        __syncthreads();  // previous chunk's frag loads done

        // A chunk: 128 rows x 16 cols -> Ash/Asl[k][m] (transpose)
#pragma unroll
        for (int i = 0; i < 2; i++) {
            int idx = tid + i * 256;           // 0..511 float4s
            int row = idx >> 2, c4 = (idx & 3) * 4;
            float4 v = *(const float4*)&A[(size_t)(bm + row) * K + k0 + c4];
            float vv[4] = {v.x, v.y, v.z, v.w};
#pragma unroll
            for (int e = 0; e < 4; e++) {
                float h = to_tf32(vv[e]);
                float l = to_tf32(vv[e] - h);
                Ash[c4 + e][row] = h;
                Asl[c4 + e][row] = l;
            }
        }
        // B chunk: 16 rows x 128 cols -> Bsh/Bsl[k][n] (direct)
#pragma unroll
        for (int i = 0; i < 2; i++) {
            int idx = tid + i * 256;           // 0..511 float4s
            int kk = idx >> 5, n4 = (idx & 31) * 4;
            float4 v = *(const float4*)&W[(size_t)(k0 + kk) * N + bn + n4];
            float4 h, l;
            h.x = to_tf32(v.x); l.x = to_tf32(v.x - h.x);
            h.y = to_tf32(v.y); l.y = to_tf32(v.y - h.y);
            h.z = to_tf32(v.z); l.z = to_tf32(v.z - h.z);
            h.w = to_tf32(v.w); l.w = to_tf32(v.w - h.w);
            *(float4*)&Bsh[kk][n4] = h;
            *(float4*)&Bsl[kk][n4] = l;
        }
        __syncthreads();

#pragma unroll
        for (int kk8 = 0; kk8 < 16; kk8 += 8) {
            uint32_t ah[2][4], al[2][4];
#pragma unroll
            for (int mt = 0; mt < 2; mt++) {
                int m0 = warp_m + mt * 16;
                ah[mt][0] = __float_as_uint(Ash[kk8 + t][m0 + g]);
                ah[mt][1] = __float_as_uint(Ash[kk8 + t][m0 + g + 8]);
                ah[mt][2] = __float_as_uint(Ash[kk8 + t + 4][m0 + g]);
                ah[mt][3] = __float_as_uint(Ash[kk8 + t + 4][m0 + g + 8]);
                al[mt][0] = __float_as_uint(Asl[kk8 + t][m0 + g]);
                al[mt][1] = __float_as_uint(Asl[kk8 + t][m0 + g + 8]);
                al[mt][2] = __float_as_uint(Asl[kk8 + t + 4][m0 + g]);
                al[mt][3] = __float_as_uint(Asl[kk8 + t + 4][m0 + g + 8]);
            }
            // pass 1+2: Bh against Ah and Al
#pragma unroll
            for (int nt = 0; nt < 8; nt++) {
                uint32_t bh[2];
                int n0 = warp_n + nt * 8 + g;
                bh[0] = __float_as_uint(Bsh[kk8 + t][n0]);
                bh[1] = __float_as_uint(Bsh[kk8 + t + 4][n0]);
#pragma unroll
                for (int mt = 0; mt < 2; mt++) {
                    mma_tf32(acc[mt][nt], ah[mt], bh);
                    mma_tf32(acc[mt][nt], al[mt], bh);
                }
            }
            // pass 3: Bl against Ah
#pragma unroll
            for (int nt = 0; nt < 8; nt++) {
                uint32_t bl[2];
                int n0 = warp_n + nt * 8 + g;
                bl[0] = __float_as_uint(Bsl[kk8 + t][n0]);
                bl[1] = __float_as_uint(Bsl[kk8 + t + 4][n0]);
#pragma unroll
                for (int mt = 0; mt < 2; mt++)
                    mma_tf32(acc[mt][nt], ah[mt], bl);
            }
        }
    }

    // Epilogue
    float* dst;
    int col0, stride;
    if (out1 && bn >= splitN) { dst = out1; col0 = bn - splitN; stride = N - splitN; }
    else if (out1)            { dst = out0; col0 = bn;          stride = splitN; }
    else                      { dst = out0; col0 = bn;          stride = N; }

#pragma unroll
    for (int mt = 0; mt < 2; mt++) {
#pragma unroll
        for (int nt = 0; nt < 8; nt++) {
            int row = bm + warp_m + mt * 16 + g;
            int col = col0 + warp_n + nt * 8 + t * 2;
            *(float2*)&dst[(size_t)row * stride + col] =
                make_float2(acc[mt][nt][0], acc[mt][nt][1]);
            *(float2*)&dst[(size_t)(row + 8) * stride + col] =
                make_float2(acc[mt][nt][2], acc[mt][nt][3]);
        }
    }
}

// ---------------------------------------------------------------------------
// Interleaved RoPE, in place. One block per row (B*T rows), 384 threads.
// ---------------------------------------------------------------------------
__global__ __launch_bounds__(384) void rope_kernel(
    float* __restrict__ t, const float* __restrict__ pos,
    const float* __restrict__ inv_freq)
{
    const int row = blockIdx.x;
    const int pr = threadIdx.x;
    const float p = pos[row];
    const float f = p * inv_freq[pr & 31];
    float s, c;
    sincosf(f, &s, &c);
    float2 v = *(float2*)&t[(size_t)row * C_ + pr * 2];
    float2 o;
    o.x = v.x * c - v.y * s;
    o.y = v.y * c + v.x * s;
    *(float2*)&t[(size_t)row * C_ + pr * 2] = o;
}

// ---------------------------------------------------------------------------
// Banded flash-attention (fp32 SIMT, unchanged from passing R0 kernel).
// ---------------------------------------------------------------------------
#define ATTN_SMEM (4 * 64 * 68 * 4)

__global__ __launch_bounds__(256) void attn_kernel(
    const float* __restrict__ xt_g, const float* __restrict__ yt_g,
    const int* __restrict__ p_dist, const int* __restrict__ p_mind)
{
    extern __shared__ float smf[];
    float(*Qs)[68] = (float(*)[68])smf;
    float(*Ks)[68] = (float(*)[68])(smf + 64 * 68);
    float(*Vs)[68] = (float(*)[68])(smf + 2 * 64 * 68);
    float(*Ps)[68] = (float(*)[68])(smf + 3 * 64 * 68);
    __shared__ float sxt[64], syt[64];
    __shared__ int s_lo, s_hi;

    const int b = blockIdx.z, h = blockIdx.y, q0 = blockIdx.x * 64;
    const int tid = threadIdx.x;
    const int tx = tid & 15, ty = tid >> 4;

    const float fdist = (float)p_dist[0];
    const float fmind = (float)p_mind[0];
    const float* yt = yt_g + (size_t)b * TY_;

    if (tid < 64) sxt[tid] = xt_g[b * TX_ + q0 + tid];

    const float* qbase = g_q + ((size_t)(b * TX_ + q0)) * C_ + h * D_;
#pragma unroll
    for (int i = 0; i < 4; i++) {
        int idx = tid + i * 256;
        int r = idx >> 4, d4 = (idx & 15) * 4;
        float4 v = *(const float4*)&qbase[(size_t)r * C_ + d4];
        Qs[d4 + 0][r] = v.x; Qs[d4 + 1][r] = v.y;
        Qs[d4 + 2][r] = v.z; Qs[d4 + 3][r] = v.w;
    }

    if (tid == 0) {
        float xlo = xt_g[b * TX_ + q0] - fmind - fdist;
        float xhi = xt_g[b * TX_ + q0 + 63] - fmind;
        int lo = 0, hi = TY_;
        while (lo < hi) { int m = (lo + hi) >> 1; if (yt[m] < xlo) lo = m + 1; else hi = m; }
        s_lo = lo;
        int lo2 = lo, hi2 = TY_;
        while (lo2 < hi2) { int m = (lo2 + hi2) >> 1; if (yt[m] <= xhi) lo2 = m + 1; else hi2 = m; }
        s_hi = lo2;
    }
    __syncthreads();

    float accO[4][4] = {};
    float m_i[4] = {-1e30f, -1e30f, -1e30f, -1e30f};
    float l_i[4] = {};

    const float* kbase = g_k + ((size_t)b * TY_) * C_ + h * D_;
    const float* vbase = g_v + ((size_t)b * TY_) * C_ + h * D_;

    const int kstart = s_lo & ~63;
    const int kend = s_hi;

    for (int k0 = kstart; k0 < kend; k0 += 64) {
        if (tid < 64) syt[tid] = yt[k0 + tid];
#pragma unroll
        for (int i = 0; i < 4; i++) {
            int idx = tid + i * 256;
            int r = idx >> 4, d4 = (idx & 15) * 4;
            size_t go = (size_t)(k0 + r) * C_ + d4;
            float4 kv = *(const float4*)&kbase[go];
            Ks[d4 + 0][r] = kv.x; Ks[d4 + 1][r] = kv.y;
            Ks[d4 + 2][r] = kv.z; Ks[d4 + 3][r] = kv.w;
            float4 vv = *(const float4*)&vbase[go];
            *(float4*)&Vs[r][d4] = vv;
        }
        __syncthreads();

        float s4[4][4] = {};
#pragma unroll
        for (int d = 0; d < 64; d++) {
            float4 a = *(const float4*)&Qs[d][ty * 4];
            float4 bb = *(const float4*)&Ks[d][tx * 4];
            s4[0][0] += a.x * bb.x; s4[0][1] += a.x * bb.y; s4[0][2] += a.x * bb.z; s4[0][3] += a.x * bb.w;
            s4[1][0] += a.y * bb.x; s4[1][1] += a.y * bb.y; s4[1][2] += a.y * bb.z; s4[1][3] += a.y * bb.w;
            s4[2][0] += a.z * bb.x; s4[2][1] += a.z * bb.y; s4[2][2] += a.z * bb.z; s4[2][3] += a.z * bb.w;
            s4[3][0] += a.w * bb.x; s4[3][1] += a.w * bb.y; s4[3][2] += a.w * bb.z; s4[3][3] += a.w * bb.w;
        }

#pragma unroll
        for (int i = 0; i < 4; i++) {
            const float xti = sxt[ty * 4 + i] - fmind;
            float rmax = -1e30f;
            float pv[4];
#pragma unroll
            for (int j = 0; j < 4; j++) {
                float ytj = syt[tx * 4 + j];
                bool valid = (xti >= ytj) && (xti <= ytj + fdist);
                float v = valid ? s4[i][j] * 0.125f : -1e30f;
                s4[i][j] = v;
                rmax = fmaxf(rmax, v);
            }
#pragma unroll
            for (int off = 8; off; off >>= 1)
                rmax = fmaxf(rmax, __shfl_xor_sync(0xffffffffu, rmax, off));
            const float mnew = fmaxf(m_i[i], rmax);
            const float alpha = __expf(m_i[i] - mnew);
            m_i[i] = mnew;
            float rs = 0.f;
#pragma unroll
            for (int j = 0; j < 4; j++) {
                float p = __expf(s4[i][j] - mnew);
                pv[j] = p;
                rs += p;
            }
#pragma unroll
            for (int off = 8; off; off >>= 1)
                rs += __shfl_xor_sync(0xffffffffu, rs, off);
            l_i[i] = l_i[i] * alpha + rs;
#pragma unroll
            for (int j = 0; j < 4; j++) accO[i][j] *= alpha;
            *(float4*)&Ps[ty * 4 + i][tx * 4] = make_float4(pv[0], pv[1], pv[2], pv[3]);
        }
        __syncthreads();

#pragma unroll 16
        for (int k = 0; k < 64; k++) {
            float4 vv = *(const float4*)&Vs[k][tx * 4];
            float a0 = Ps[ty * 4 + 0][k];
            float a1 = Ps[ty * 4 + 1][k];
            float a2 = Ps[ty * 4 + 2][k];
            float a3 = Ps[ty * 4 + 3][k];
            accO[0][0] += a0 * vv.x; accO[0][1] += a0 * vv.y; accO[0][2] += a0 * vv.z; accO[0][3] += a0 * vv.w;
            accO[1][0] += a1 * vv.x; accO[1][1] += a1 * vv.y; accO[1][2] += a1 * vv.z; accO[1][3] += a1 * vv.w;
            accO[2][0] += a2 * vv.x; accO[2][1] += a2 * vv.y; accO[2][2] += a2 * vv.z; accO[2][3] += a2 * vv.w;
            accO[3][0] += a3 * vv.x; accO[3][1] += a3 * vv.y; accO[3][2] += a3 * vv.z; accO[3][3] += a3 * vv.w;
        }
        __syncthreads();
    }

    float* obase = g_o + ((size_t)(b * TX_ + q0)) * C_ + h * D_;
#pragma unroll
    for (int i = 0; i < 4; i++) {
        float inv = 1.f / l_i[i];
        float4 r = make_float4(accO[i][0] * inv, accO[i][1] * inv,
                               accO[i][2] * inv, accO[i][3] * inv);
        *(float4*)&obase[(size_t)(ty * 4 + i) * C_ + tx * 4] = r;
    }
}

// ---------------------------------------------------------------------------
// Launch
// inputs: 0 x, 1 x_t, 2 y, 3 y_t, 4 dist, 5 min_dist, 6 Wq, 7 Wkv, 8 Wproj, 9 inv_freq
// ---------------------------------------------------------------------------
extern "C" void kernel_launch(void* const* d_in, const int* in_sizes, int n_in,
                              void* d_out, int out_size)
{
    const float* x        = (const float*)d_in[0];
    const float* x_t      = (const float*)d_in[1];
    const float* y        = (const float*)d_in[2];
    const float* y_t      = (const float*)d_in[3];
    const int*   dist     = (const int*)d_in[4];
    const int*   mind     = (const int*)d_in[5];
    const float* Wq       = (const float*)d_in[6];
    const float* Wkv      = (const float*)d_in[7];
    const float* Wproj    = (const float*)d_in[8];
    const float* inv_freq = (const float*)d_in[9];
    float* out = (float*)d_out;

    float *q_p, *k_p, *v_p, *o_p;
    cudaGetSymbolAddress((void**)&q_p, g_q);
    cudaGetSymbolAddress((void**)&k_p, g_k);
    cudaGetSymbolAddress((void**)&v_p, g_v);
    cudaGetSymbolAddress((void**)&o_p, g_o);

    cudaFuncSetAttribute(attn_kernel, cudaFuncAttributeMaxDynamicSharedMemorySize, ATTN_SMEM);

    // q = x @ Wq   [2048,768] x [768,768]
    gemm_tc<<<dim3(C_ / 128, (B_ * TX_) / 128), 256>>>(x, Wq, q_p, nullptr, C_, C_, 0);
    // kv = y @ Wkv [8192,768] x [768,1536] -> split into k, v
    gemm_tc<<<dim3(2 * C_ / 128, (B_ * TY_) / 128), 256>>>(y, Wkv, k_p, v_p, 2 * C_, C_, C_);
    // RoPE
    rope_kernel<<<B_ * TX_, 384>>>(q_p, x_t, inv_freq);
    rope_kernel<<<B_ * TY_, 384>>>(k_p, y_t, inv_freq);
    // banded flash attention
    attn_kernel<<<dim3(TX_ / 64, H_, B_), 256, ATTN_SMEM>>>(x_t, y_t, dist, mind);
    // final projection: out = o @ Wproj
    gemm_tc<<<dim3(C_ / 128, (B_ * TX_) / 128), 256>>>(o_p, Wproj, out, nullptr, C_, C_, 0);
}

// round 8
// speedup vs baseline: 2.1194x; 2.1194x over previous
#include <cuda_runtime.h>
#include <cuda_fp16.h>
#include <math.h>
#include <stdint.h>

// Problem constants
#define B_   2
#define TX_  1024
#define TY_  4096
#define C_   768
#define H_   12
#define D_   64

// Scratch (device globals: no allocation allowed)
__device__ float g_q[B_ * TX_ * C_];
__device__ float g_k[B_ * TY_ * C_];
__device__ float g_v[B_ * TY_ * C_];
__device__ float g_o[B_ * TX_ * C_];

// ---------------------------------------------------------------------------
// mma / ldmatrix helpers (sm_80-era instructions, valid on base sm_103)
// ---------------------------------------------------------------------------
__device__ __forceinline__ void mma_f16(float* d, const uint32_t* a, const uint32_t* b) {
    asm volatile(
        "mma.sync.aligned.m16n8k16.row.col.f32.f16.f16.f32 "
        "{%0,%1,%2,%3}, {%4,%5,%6,%7}, {%8,%9}, {%0,%1,%2,%3};"
        : "+f"(d[0]), "+f"(d[1]), "+f"(d[2]), "+f"(d[3])
        : "r"(a[0]), "r"(a[1]), "r"(a[2]), "r"(a[3]), "r"(b[0]), "r"(b[1]));
}

__device__ __forceinline__ void ldsm_x4(uint32_t& r0, uint32_t& r1, uint32_t& r2,
                                        uint32_t& r3, uint32_t addr) {
    asm volatile("ldmatrix.sync.aligned.m8n8.x4.shared.b16 {%0,%1,%2,%3}, [%4];"
                 : "=r"(r0), "=r"(r1), "=r"(r2), "=r"(r3) : "r"(addr));
}

__device__ __forceinline__ void ldsm_x4_trans(uint32_t& r0, uint32_t& r1, uint32_t& r2,
                                              uint32_t& r3, uint32_t addr) {
    asm volatile("ldmatrix.sync.aligned.m8n8.x4.trans.shared.b16 {%0,%1,%2,%3}, [%4];"
                 : "=r"(r0), "=r"(r1), "=r"(r2), "=r"(r3) : "r"(addr));
}

// ---------------------------------------------------------------------------
// Tensor-core fp16 GEMM (single-pass, fp32 accumulate).
// out = A[M,K] @ W[K,N], fp32 in/out. Block tile 128x128, 256 threads,
// 8 warps (4m x 2n), warp tile 32x64 = 2x8 m16n8k16 fragments. K-chunk = 32.
// Fragments via ldmatrix: A from [m][k] smem (non-trans), B from [k][n]
// smem (.trans). If out1 != nullptr: cols [0,splitN) -> out0, rest -> out1.
// ---------------------------------------------------------------------------
#define AROW 40    // halfs per A smem row (32 + 8 pad -> 80B, conflict-free ldsm)
#define BROW 136   // halfs per B smem row (128 + 8 pad -> 272B, conflict-free ldsm)

__global__ __launch_bounds__(256, 1) void gemm_tc(
    const float* __restrict__ A, const float* __restrict__ W,
    float* __restrict__ out0, float* __restrict__ out1,
    int N, int K, int splitN)
{
    __shared__ __half Asm[128 * AROW];  // [m][k]
    __shared__ __half Bsm[32 * BROW];   // [k][n]

    const int tid = threadIdx.x;
    const int wid = tid >> 5, lane = tid & 31;
    const int g = lane >> 2, t = lane & 3;
    const int warp_m = (wid >> 1) * 32;   // 0,32,64,96
    const int warp_n = (wid & 1) * 64;    // 0,64
    const int bn = blockIdx.x * 128, bm = blockIdx.y * 128;

    float acc[2][8][4];
#pragma unroll
    for (int mt = 0; mt < 2; mt++)
#pragma unroll
        for (int nt = 0; nt < 8; nt++)
#pragma unroll
            for (int e = 0; e < 4; e++) acc[mt][nt][e] = 0.f;

    const uint32_t a_base = (uint32_t)__cvta_generic_to_shared(Asm);
    const uint32_t b_base = (uint32_t)__cvta_generic_to_shared(Bsm);

    // ldmatrix lane addresses (bytes)
    // A (x4, non-trans): tile rows = m, lanes 0-15 -> m rows, lanes 16-31 -> k+8 halfs
    const uint32_t a_addr0 = a_base + (uint32_t)(warp_m + (lane & 15)) * (AROW * 2)
                                    + (uint32_t)(lane >> 4) * 16;
    const uint32_t a_addr1 = a_addr0 + 16 * (AROW * 2);
    // B (x4, trans): lanes 0-15 -> k rows, lanes 16-31 -> n+8
    const uint32_t b_addr_base = b_base + (uint32_t)(lane & 15) * (BROW * 2)
                                        + (uint32_t)(warp_n + (lane >> 4) * 8) * 2;

    const int nch = K / 32;
    for (int c = 0; c < nch; c++) {
        const int k0 = c * 32;
        __syncthreads();  // previous chunk's ldmatrix reads complete

        // A chunk: 128 rows x 32 cols fp32 -> fp16 smem [m][k]
#pragma unroll
        for (int i = 0; i < 4; i++) {
            int idx = tid + i * 256;            // 0..1023 float4s
            int row = idx >> 3, c4 = (idx & 7) * 4;
            float4 v = *(const float4*)&A[(size_t)(bm + row) * K + k0 + c4];
            __half2* dst = (__half2*)&Asm[row * AROW + c4];
            dst[0] = __floats2half2_rn(v.x, v.y);
            dst[1] = __floats2half2_rn(v.z, v.w);
        }
        // B chunk: 32 rows x 128 cols fp32 -> fp16 smem [k][n]
#pragma unroll
        for (int i = 0; i < 4; i++) {
            int idx = tid + i * 256;            // 0..1023 float4s
            int kk = idx >> 5, n4 = (idx & 31) * 4;
            float4 v = *(const float4*)&W[(size_t)(k0 + kk) * N + bn + n4];
            __half2* dst = (__half2*)&Bsm[kk * BROW + n4];
            dst[0] = __floats2half2_rn(v.x, v.y);
            dst[1] = __floats2half2_rn(v.z, v.w);
        }
        __syncthreads();

#pragma unroll
        for (int kk16 = 0; kk16 < 32; kk16 += 16) {
            uint32_t af[2][4];
            ldsm_x4(af[0][0], af[0][1], af[0][2], af[0][3], a_addr0 + kk16 * 2);
            ldsm_x4(af[1][0], af[1][1], af[1][2], af[1][3], a_addr1 + kk16 * 2);

            uint32_t bf[8][2];
#pragma unroll
            for (int p = 0; p < 4; p++) {
                ldsm_x4_trans(bf[2 * p][0], bf[2 * p][1], bf[2 * p + 1][0], bf[2 * p + 1][1],
                              b_addr_base + (uint32_t)kk16 * (BROW * 2) + (uint32_t)p * 32);
            }
#pragma unroll
            for (int nt = 0; nt < 8; nt++) {
#pragma unroll
                for (int mt = 0; mt < 2; mt++)
                    mma_f16(acc[mt][nt], af[mt], bf[nt]);
            }
        }
    }

    // Epilogue
    float* dst;
    int col0, stride;
    if (out1 && bn >= splitN) { dst = out1; col0 = bn - splitN; stride = N - splitN; }
    else if (out1)            { dst = out0; col0 = bn;          stride = splitN; }
    else                      { dst = out0; col0 = bn;          stride = N; }

#pragma unroll
    for (int mt = 0; mt < 2; mt++) {
#pragma unroll
        for (int nt = 0; nt < 8; nt++) {
            int row = bm + warp_m + mt * 16 + g;
            int col = col0 + warp_n + nt * 8 + t * 2;
            *(float2*)&dst[(size_t)row * stride + col] =
                make_float2(acc[mt][nt][0], acc[mt][nt][1]);
            *(float2*)&dst[(size_t)(row + 8) * stride + col] =
                make_float2(acc[mt][nt][2], acc[mt][nt][3]);
        }
    }
}

// ---------------------------------------------------------------------------
// Interleaved RoPE, in place. One block per row (B*T rows), 384 threads.
// ---------------------------------------------------------------------------
__global__ __launch_bounds__(384) void rope_kernel(
    float* __restrict__ t, const float* __restrict__ pos,
    const float* __restrict__ inv_freq)
{
    const int row = blockIdx.x;
    const int pr = threadIdx.x;
    const float p = pos[row];
    const float f = p * inv_freq[pr & 31];
    float s, c;
    sincosf(f, &s, &c);
    float2 v = *(float2*)&t[(size_t)row * C_ + pr * 2];
    float2 o;
    o.x = v.x * c - v.y * s;
    o.y = v.y * c + v.x * s;
    *(float2*)&t[(size_t)row * C_ + pr * 2] = o;
}

// ---------------------------------------------------------------------------
// Banded flash-attention (fp32 SIMT, unchanged from passing R0 kernel).
// ---------------------------------------------------------------------------
#define ATTN_SMEM (4 * 64 * 68 * 4)

__global__ __launch_bounds__(256) void attn_kernel(
    const float* __restrict__ xt_g, const float* __restrict__ yt_g,
    const int* __restrict__ p_dist, const int* __restrict__ p_mind)
{
    extern __shared__ float smf[];
    float(*Qs)[68] = (float(*)[68])smf;
    float(*Ks)[68] = (float(*)[68])(smf + 64 * 68);
    float(*Vs)[68] = (float(*)[68])(smf + 2 * 64 * 68);
    float(*Ps)[68] = (float(*)[68])(smf + 3 * 64 * 68);
    __shared__ float sxt[64], syt[64];
    __shared__ int s_lo, s_hi;

    const int b = blockIdx.z, h = blockIdx.y, q0 = blockIdx.x * 64;
    const int tid = threadIdx.x;
    const int tx = tid & 15, ty = tid >> 4;

    const float fdist = (float)p_dist[0];
    const float fmind = (float)p_mind[0];
    const float* yt = yt_g + (size_t)b * TY_;

    if (tid < 64) sxt[tid] = xt_g[b * TX_ + q0 + tid];

    const float* qbase = g_q + ((size_t)(b * TX_ + q0)) * C_ + h * D_;
#pragma unroll
    for (int i = 0; i < 4; i++) {
        int idx = tid + i * 256;
        int r = idx >> 4, d4 = (idx & 15) * 4;
        float4 v = *(const float4*)&qbase[(size_t)r * C_ + d4];
        Qs[d4 + 0][r] = v.x; Qs[d4 + 1][r] = v.y;
        Qs[d4 + 2][r] = v.z; Qs[d4 + 3][r] = v.w;
    }

    if (tid == 0) {
        float xlo = xt_g[b * TX_ + q0] - fmind - fdist;
        float xhi = xt_g[b * TX_ + q0 + 63] - fmind;
        int lo = 0, hi = TY_;
        while (lo < hi) { int m = (lo + hi) >> 1; if (yt[m] < xlo) lo = m + 1; else hi = m; }
        s_lo = lo;
        int lo2 = lo, hi2 = TY_;
        while (lo2 < hi2) { int m = (lo2 + hi2) >> 1; if (yt[m] <= xhi) lo2 = m + 1; else hi2 = m; }
        s_hi = lo2;
    }
    __syncthreads();

    float accO[4][4] = {};
    float m_i[4] = {-1e30f, -1e30f, -1e30f, -1e30f};
    float l_i[4] = {};

    const float* kbase = g_k + ((size_t)b * TY_) * C_ + h * D_;
    const float* vbase = g_v + ((size_t)b * TY_) * C_ + h * D_;

    const int kstart = s_lo & ~63;
    const int kend = s_hi;

    for (int k0 = kstart; k0 < kend; k0 += 64) {
        if (tid < 64) syt[tid] = yt[k0 + tid];
#pragma unroll
        for (int i = 0; i < 4; i++) {
            int idx = tid + i * 256;
            int r = idx >> 4, d4 = (idx & 15) * 4;
            size_t go = (size_t)(k0 + r) * C_ + d4;
            float4 kv = *(const float4*)&kbase[go];
            Ks[d4 + 0][r] = kv.x; Ks[d4 + 1][r] = kv.y;
            Ks[d4 + 2][r] = kv.z; Ks[d4 + 3][r] = kv.w;
            float4 vv = *(const float4*)&vbase[go];
            *(float4*)&Vs[r][d4] = vv;
        }
        __syncthreads();

        float s4[4][4] = {};
#pragma unroll
        for (int d = 0; d < 64; d++) {
            float4 a = *(const float4*)&Qs[d][ty * 4];
            float4 bb = *(const float4*)&Ks[d][tx * 4];
            s4[0][0] += a.x * bb.x; s4[0][1] += a.x * bb.y; s4[0][2] += a.x * bb.z; s4[0][3] += a.x * bb.w;
            s4[1][0] += a.y * bb.x; s4[1][1] += a.y * bb.y; s4[1][2] += a.y * bb.z; s4[1][3] += a.y * bb.w;
            s4[2][0] += a.z * bb.x; s4[2][1] += a.z * bb.y; s4[2][2] += a.z * bb.z; s4[2][3] += a.z * bb.w;
            s4[3][0] += a.w * bb.x; s4[3][1] += a.w * bb.y; s4[3][2] += a.w * bb.z; s4[3][3] += a.w * bb.w;
        }

#pragma unroll
        for (int i = 0; i < 4; i++) {
            const float xti = sxt[ty * 4 + i] - fmind;
            float rmax = -1e30f;
            float pv[4];
#pragma unroll
            for (int j = 0; j < 4; j++) {
                float ytj = syt[tx * 4 + j];
                bool valid = (xti >= ytj) && (xti <= ytj + fdist);
                float v = valid ? s4[i][j] * 0.125f : -1e30f;
                s4[i][j] = v;
                rmax = fmaxf(rmax, v);
            }
#pragma unroll
            for (int off = 8; off; off >>= 1)
                rmax = fmaxf(rmax, __shfl_xor_sync(0xffffffffu, rmax, off));
            const float mnew = fmaxf(m_i[i], rmax);
            const float alpha = __expf(m_i[i] - mnew);
            m_i[i] = mnew;
            float rs = 0.f;
#pragma unroll
            for (int j = 0; j < 4; j++) {
                float p = __expf(s4[i][j] - mnew);
                pv[j] = p;
                rs += p;
            }
#pragma unroll
            for (int off = 8; off; off >>= 1)
                rs += __shfl_xor_sync(0xffffffffu, rs, off);
            l_i[i] = l_i[i] * alpha + rs;
#pragma unroll
            for (int j = 0; j < 4; j++) accO[i][j] *= alpha;
            *(float4*)&Ps[ty * 4 + i][tx * 4] = make_float4(pv[0], pv[1], pv[2], pv[3]);
        }
        __syncthreads();

#pragma unroll 16
        for (int k = 0; k < 64; k++) {
            float4 vv = *(const float4*)&Vs[k][tx * 4];
            float a0 = Ps[ty * 4 + 0][k];
            float a1 = Ps[ty * 4 + 1][k];
            float a2 = Ps[ty * 4 + 2][k];
            float a3 = Ps[ty * 4 + 3][k];
            accO[0][0] += a0 * vv.x; accO[0][1] += a0 * vv.y; accO[0][2] += a0 * vv.z; accO[0][3] += a0 * vv.w;
            accO[1][0] += a1 * vv.x; accO[1][1] += a1 * vv.y; accO[1][2] += a1 * vv.z; accO[1][3] += a1 * vv.w;
            accO[2][0] += a2 * vv.x; accO[2][1] += a2 * vv.y; accO[2][2] += a2 * vv.z; accO[2][3] += a2 * vv.w;
            accO[3][0] += a3 * vv.x; accO[3][1] += a3 * vv.y; accO[3][2] += a3 * vv.z; accO[3][3] += a3 * vv.w;
        }
        __syncthreads();
    }

    float* obase = g_o + ((size_t)(b * TX_ + q0)) * C_ + h * D_;
#pragma unroll
    for (int i = 0; i < 4; i++) {
        float inv = 1.f / l_i[i];
        float4 r = make_float4(accO[i][0] * inv, accO[i][1] * inv,
                               accO[i][2] * inv, accO[i][3] * inv);
        *(float4*)&obase[(size_t)(ty * 4 + i) * C_ + tx * 4] = r;
    }
}

// ---------------------------------------------------------------------------
// Launch
// inputs: 0 x, 1 x_t, 2 y, 3 y_t, 4 dist, 5 min_dist, 6 Wq, 7 Wkv, 8 Wproj, 9 inv_freq
// ---------------------------------------------------------------------------
extern "C" void kernel_launch(void* const* d_in, const int* in_sizes, int n_in,
                              void* d_out, int out_size)
{
    const float* x        = (const float*)d_in[0];
    const float* x_t      = (const float*)d_in[1];
    const float* y        = (const float*)d_in[2];
    const float* y_t      = (const float*)d_in[3];
    const int*   dist     = (const int*)d_in[4];
    const int*   mind     = (const int*)d_in[5];
    const float* Wq       = (const float*)d_in[6];
    const float* Wkv      = (const float*)d_in[7];
    const float* Wproj    = (const float*)d_in[8];
    const float* inv_freq = (const float*)d_in[9];
    float* out = (float*)d_out;

    float *q_p, *k_p, *v_p, *o_p;
    cudaGetSymbolAddress((void**)&q_p, g_q);
    cudaGetSymbolAddress((void**)&k_p, g_k);
    cudaGetSymbolAddress((void**)&v_p, g_v);
    cudaGetSymbolAddress((void**)&o_p, g_o);

    cudaFuncSetAttribute(attn_kernel, cudaFuncAttributeMaxDynamicSharedMemorySize, ATTN_SMEM);

    // q = x @ Wq   [2048,768] x [768,768]
    gemm_tc<<<dim3(C_ / 128, (B_ * TX_) / 128), 256>>>(x, Wq, q_p, nullptr, C_, C_, 0);
    // kv = y @ Wkv [8192,768] x [768,1536] -> split into k, v
    gemm_tc<<<dim3(2 * C_ / 128, (B_ * TY_) / 128), 256>>>(y, Wkv, k_p, v_p, 2 * C_, C_, C_);
    // RoPE
    rope_kernel<<<B_ * TX_, 384>>>(q_p, x_t, inv_freq);
    rope_kernel<<<B_ * TY_, 384>>>(k_p, y_t, inv_freq);
    // banded flash attention
    attn_kernel<<<dim3(TX_ / 64, H_, B_), 256, ATTN_SMEM>>>(x_t, y_t, dist, mind);
    // final projection: out = o @ Wproj
    gemm_tc<<<dim3(C_ / 128, (B_ * TX_) / 128), 256>>>(o_p, Wproj, out, nullptr, C_, C_, 0);
}

// round 10
// speedup vs baseline: 3.2324x; 1.5252x over previous
#include <cuda_runtime.h>
#include <cuda_fp16.h>
#include <math.h>
#include <stdint.h>

// Problem constants
#define B_   2
#define TX_  1024
#define TY_  4096
#define C_   768
#define H_   12
#define D_   64

// Scratch (device globals: no allocation allowed)
__device__ float g_q[B_ * TX_ * C_];
__device__ float g_k[B_ * TY_ * C_];
__device__ float g_v[B_ * TY_ * C_];
__device__ float g_o[B_ * TX_ * C_];

// ---------------------------------------------------------------------------
// mma / ldmatrix helpers (sm_80-era instructions, valid on base sm_103)
// ---------------------------------------------------------------------------
__device__ __forceinline__ void mma_f16(float* d, const uint32_t* a, const uint32_t* b) {
    asm volatile(
        "mma.sync.aligned.m16n8k16.row.col.f32.f16.f16.f32 "
        "{%0,%1,%2,%3}, {%4,%5,%6,%7}, {%8,%9}, {%0,%1,%2,%3};"
        : "+f"(d[0]), "+f"(d[1]), "+f"(d[2]), "+f"(d[3])
        : "r"(a[0]), "r"(a[1]), "r"(a[2]), "r"(a[3]), "r"(b[0]), "r"(b[1]));
}

__device__ __forceinline__ void ldsm_x4(uint32_t& r0, uint32_t& r1, uint32_t& r2,
                                        uint32_t& r3, uint32_t addr) {
    asm volatile("ldmatrix.sync.aligned.m8n8.x4.shared.b16 {%0,%1,%2,%3}, [%4];"
                 : "=r"(r0), "=r"(r1), "=r"(r2), "=r"(r3) : "r"(addr));
}

__device__ __forceinline__ void ldsm_x4_trans(uint32_t& r0, uint32_t& r1, uint32_t& r2,
                                              uint32_t& r3, uint32_t addr) {
    asm volatile("ldmatrix.sync.aligned.m8n8.x4.trans.shared.b16 {%0,%1,%2,%3}, [%4];"
                 : "=r"(r0), "=r"(r1), "=r"(r2), "=r"(r3) : "r"(addr));
}

__device__ __forceinline__ uint32_t h2pack(float a, float b) {
    __half2 h = __floats2half2_rn(a, b);
    return *(uint32_t*)&h;
}

// ---------------------------------------------------------------------------
// Tensor-core fp16 GEMM (single-pass, fp32 accumulate). Unchanged from R7.
// ---------------------------------------------------------------------------
#define AROW 40
#define BROW 136

__global__ __launch_bounds__(256, 1) void gemm_tc(
    const float* __restrict__ A, const float* __restrict__ W,
    float* __restrict__ out0, float* __restrict__ out1,
    int N, int K, int splitN)
{
    __shared__ __half Asm[128 * AROW];  // [m][k]
    __shared__ __half Bsm[32 * BROW];   // [k][n]

    const int tid = threadIdx.x;
    const int wid = tid >> 5, lane = tid & 31;
    const int g = lane >> 2, t = lane & 3;
    const int warp_m = (wid >> 1) * 32;
    const int warp_n = (wid & 1) * 64;
    const int bn = blockIdx.x * 128, bm = blockIdx.y * 128;

    float acc[2][8][4];
#pragma unroll
    for (int mt = 0; mt < 2; mt++)
#pragma unroll
        for (int nt = 0; nt < 8; nt++)
#pragma unroll
            for (int e = 0; e < 4; e++) acc[mt][nt][e] = 0.f;

    const uint32_t a_base = (uint32_t)__cvta_generic_to_shared(Asm);
    const uint32_t b_base = (uint32_t)__cvta_generic_to_shared(Bsm);

    const uint32_t a_addr0 = a_base + (uint32_t)(warp_m + (lane & 15)) * (AROW * 2)
                                    + (uint32_t)(lane >> 4) * 16;
    const uint32_t a_addr1 = a_addr0 + 16 * (AROW * 2);
    const uint32_t b_addr_base = b_base + (uint32_t)(lane & 15) * (BROW * 2)
                                        + (uint32_t)(warp_n + (lane >> 4) * 8) * 2;

    const int nch = K / 32;
    for (int c = 0; c < nch; c++) {
        const int k0 = c * 32;
        __syncthreads();

#pragma unroll
        for (int i = 0; i < 4; i++) {
            int idx = tid + i * 256;
            int row = idx >> 3, c4 = (idx & 7) * 4;
            float4 v = *(const float4*)&A[(size_t)(bm + row) * K + k0 + c4];
            __half2* dst = (__half2*)&Asm[row * AROW + c4];
            dst[0] = __floats2half2_rn(v.x, v.y);
            dst[1] = __floats2half2_rn(v.z, v.w);
        }
#pragma unroll
        for (int i = 0; i < 4; i++) {
            int idx = tid + i * 256;
            int kk = idx >> 5, n4 = (idx & 31) * 4;
            float4 v = *(const float4*)&W[(size_t)(k0 + kk) * N + bn + n4];
            __half2* dst = (__half2*)&Bsm[kk * BROW + n4];
            dst[0] = __floats2half2_rn(v.x, v.y);
            dst[1] = __floats2half2_rn(v.z, v.w);
        }
        __syncthreads();

#pragma unroll
        for (int kk16 = 0; kk16 < 32; kk16 += 16) {
            uint32_t af[2][4];
            ldsm_x4(af[0][0], af[0][1], af[0][2], af[0][3], a_addr0 + kk16 * 2);
            ldsm_x4(af[1][0], af[1][1], af[1][2], af[1][3], a_addr1 + kk16 * 2);

            uint32_t bf[8][2];
#pragma unroll
            for (int p = 0; p < 4; p++) {
                ldsm_x4_trans(bf[2 * p][0], bf[2 * p][1], bf[2 * p + 1][0], bf[2 * p + 1][1],
                              b_addr_base + (uint32_t)kk16 * (BROW * 2) + (uint32_t)p * 32);
            }
#pragma unroll
            for (int nt = 0; nt < 8; nt++) {
#pragma unroll
                for (int mt = 0; mt < 2; mt++)
                    mma_f16(acc[mt][nt], af[mt], bf[nt]);
            }
        }
    }

    float* dst;
    int col0, stride;
    if (out1 && bn >= splitN) { dst = out1; col0 = bn - splitN; stride = N - splitN; }
    else if (out1)            { dst = out0; col0 = bn;          stride = splitN; }
    else                      { dst = out0; col0 = bn;          stride = N; }

#pragma unroll
    for (int mt = 0; mt < 2; mt++) {
#pragma unroll
        for (int nt = 0; nt < 8; nt++) {
            int row = bm + warp_m + mt * 16 + g;
            int col = col0 + warp_n + nt * 8 + t * 2;
            *(float2*)&dst[(size_t)row * stride + col] =
                make_float2(acc[mt][nt][0], acc[mt][nt][1]);
            *(float2*)&dst[(size_t)(row + 8) * stride + col] =
                make_float2(acc[mt][nt][2], acc[mt][nt][3]);
        }
    }
}

// ---------------------------------------------------------------------------
// Interleaved RoPE, in place.
// ---------------------------------------------------------------------------
__global__ __launch_bounds__(384) void rope_kernel(
    float* __restrict__ t, const float* __restrict__ pos,
    const float* __restrict__ inv_freq)
{
    const int row = blockIdx.x;
    const int pr = threadIdx.x;
    const float p = pos[row];
    const float f = p * inv_freq[pr & 31];
    float s, c;
    sincosf(f, &s, &c);
    float2 v = *(float2*)&t[(size_t)row * C_ + pr * 2];
    float2 o;
    o.x = v.x * c - v.y * s;
    o.y = v.y * c + v.x * s;
    *(float2*)&t[(size_t)row * C_ + pr * 2] = o;
}

// ---------------------------------------------------------------------------
// Banded flash-attention, fp16 tensor cores, fp32 accumulate + softmax.
// Block = (b, h, 64-query tile), 128 threads = 4 warps, warp handles m16.
// Q smem [q][d] (scaled by 1/8), K smem [key][d], V smem [key][d], fp16.
// QK^T: A = Q (ldsm x4), B = K via non-trans ldsm on [n][k] layout.
// PV: A = P (from S accum frags, half2-packed), B = V via trans ldsm.
// ---------------------------------------------------------------------------
#define QROW 72   // halfs per smem row (64 + 8 pad, 144B)

__global__ __launch_bounds__(128) void attn_tc(
    const float* __restrict__ xt_g, const float* __restrict__ yt_g,
    const int* __restrict__ p_dist, const int* __restrict__ p_mind)
{
    __shared__ __align__(16) __half Qh[64 * QROW];
    __shared__ __align__(16) __half Kh[64 * QROW];
    __shared__ __align__(16) __half Vh[64 * QROW];
    __shared__ float sxt[64], syt[64];
    __shared__ int s_lo, s_hi;

    const int b = blockIdx.z, h = blockIdx.y, q0 = blockIdx.x * 64;
    const int tid = threadIdx.x;
    const int wid = tid >> 5, lane = tid & 31;
    const int g = lane >> 2, t = lane & 3;
    const int warp_q = wid * 16;

    const float fdist = (float)p_dist[0];
    const float fmind = (float)p_mind[0];
    const float* yt = yt_g + (size_t)b * TY_;

    // Q tile: 64x64 fp32 -> fp16 smem [q][d], scaled by 1/sqrt(D)=0.125
    const float* qbase = g_q + ((size_t)(b * TX_ + q0)) * C_ + h * D_;
#pragma unroll
    for (int i = 0; i < 8; i++) {
        int idx = tid + i * 128;            // 0..1023 float4s
        int row = idx >> 4, c4 = (idx & 15) * 4;
        float4 v = *(const float4*)&qbase[(size_t)row * C_ + c4];
        __half2* dst = (__half2*)&Qh[row * QROW + c4];
        dst[0] = __floats2half2_rn(v.x * 0.125f, v.y * 0.125f);
        dst[1] = __floats2half2_rn(v.z * 0.125f, v.w * 0.125f);
    }
    if (tid < 64) sxt[tid] = xt_g[b * TX_ + q0 + tid];

    if (tid == 0) {
        float xlo = xt_g[b * TX_ + q0] - fmind - fdist;
        float xhi = xt_g[b * TX_ + q0 + 63] - fmind;
        int lo = 0, hi = TY_;
        while (lo < hi) { int m = (lo + hi) >> 1; if (yt[m] < xlo) lo = m + 1; else hi = m; }
        s_lo = lo;
        int lo2 = lo, hi2 = TY_;
        while (lo2 < hi2) { int m = (lo2 + hi2) >> 1; if (yt[m] <= xhi) lo2 = m + 1; else hi2 = m; }
        s_hi = lo2;
    }
    __syncthreads();

    const uint32_t qb = (uint32_t)__cvta_generic_to_shared(Qh);
    const uint32_t kb = (uint32_t)__cvta_generic_to_shared(Kh);
    const uint32_t vb = (uint32_t)__cvta_generic_to_shared(Vh);

    // A-frag addr (Q, [m][k], non-trans)
    const uint32_t a_addr = qb + (uint32_t)(warp_q + (lane & 15)) * (QROW * 2)
                               + (uint32_t)(lane >> 4) * 16;
    // K B-frag addr (non-trans on [n=key][k=d])
    const uint32_t key_off = ((lane >> 4) << 3) + (lane & 7);
    const uint32_t d_off = ((lane >> 3) & 1) << 3;
    const uint32_t k_addr = kb + key_off * (QROW * 2) + d_off * 2;
    // V B-frag addr (trans on [k=key][n=d])
    const uint32_t v_addr = vb + (uint32_t)(lane & 15) * (QROW * 2)
                               + (uint32_t)(lane >> 4) * 16;

    float oacc[8][4];
#pragma unroll
    for (int j = 0; j < 8; j++)
#pragma unroll
        for (int e = 0; e < 4; e++) oacc[j][e] = 0.f;
    float m0 = -1e30f, m1 = -1e30f, l0 = 0.f, l1 = 0.f;

    const float* kbase = g_k + ((size_t)b * TY_) * C_ + h * D_;
    const float* vbase = g_v + ((size_t)b * TY_) * C_ + h * D_;

    const int kstart = s_lo & ~63;
    const int kend = s_hi;
    const float xti0 = sxt[warp_q + g] - fmind;
    const float xti1 = sxt[warp_q + g + 8] - fmind;

    for (int k0 = kstart; k0 < kend; k0 += 64) {
        __syncthreads();   // previous tile's ldsm reads complete
        if (tid < 64) syt[tid] = yt[k0 + tid];
#pragma unroll
        for (int i = 0; i < 8; i++) {
            int idx = tid + i * 128;
            int row = idx >> 4, c4 = (idx & 15) * 4;
            size_t go = (size_t)(k0 + row) * C_ + c4;
            float4 kv = *(const float4*)&kbase[go];
            __half2* kd = (__half2*)&Kh[row * QROW + c4];
            kd[0] = __floats2half2_rn(kv.x, kv.y);
            kd[1] = __floats2half2_rn(kv.z, kv.w);
            float4 vv = *(const float4*)&vbase[go];
            __half2* vd = (__half2*)&Vh[row * QROW + c4];
            vd[0] = __floats2half2_rn(vv.x, vv.y);
            vd[1] = __floats2half2_rn(vv.z, vv.w);
        }
        __syncthreads();

        // ---- S = Q K^T (64 keys x 16 rows per warp) ----
        uint32_t af[4][4];
#pragma unroll
        for (int ks = 0; ks < 4; ks++)
            ldsm_x4(af[ks][0], af[ks][1], af[ks][2], af[ks][3], a_addr + ks * 32);

        float sacc[8][4];
#pragma unroll
        for (int j = 0; j < 8; j++)
#pragma unroll
            for (int e = 0; e < 4; e++) sacc[j][e] = 0.f;

#pragma unroll
        for (int ks = 0; ks < 4; ks++) {
#pragma unroll
            for (int p = 0; p < 4; p++) {
                uint32_t b0, b1, b2, b3;
                ldsm_x4(b0, b1, b2, b3, k_addr + (uint32_t)p * (16 * QROW * 2) + (uint32_t)ks * 32);
                uint32_t bf0[2] = {b0, b1}, bf1[2] = {b2, b3};
                mma_f16(sacc[2 * p], af[ks], bf0);
                mma_f16(sacc[2 * p + 1], af[ks], bf1);
            }
        }

        // ---- mask + online softmax (rows g and g+8) ----
        float rmax0 = -1e30f, rmax1 = -1e30f;
#pragma unroll
        for (int j = 0; j < 8; j++) {
            float yt0 = syt[8 * j + 2 * t];
            float yt1 = syt[8 * j + 2 * t + 1];
            sacc[j][0] = (xti0 >= yt0 && xti0 <= yt0 + fdist) ? sacc[j][0] : -1e30f;
            sacc[j][1] = (xti0 >= yt1 && xti0 <= yt1 + fdist) ? sacc[j][1] : -1e30f;
            sacc[j][2] = (xti1 >= yt0 && xti1 <= yt0 + fdist) ? sacc[j][2] : -1e30f;
            sacc[j][3] = (xti1 >= yt1 && xti1 <= yt1 + fdist) ? sacc[j][3] : -1e30f;
            rmax0 = fmaxf(rmax0, fmaxf(sacc[j][0], sacc[j][1]));
            rmax1 = fmaxf(rmax1, fmaxf(sacc[j][2], sacc[j][3]));
        }
        rmax0 = fmaxf(rmax0, __shfl_xor_sync(0xffffffffu, rmax0, 1));
        rmax0 = fmaxf(rmax0, __shfl_xor_sync(0xffffffffu, rmax0, 2));
        rmax1 = fmaxf(rmax1, __shfl_xor_sync(0xffffffffu, rmax1, 1));
        rmax1 = fmaxf(rmax1, __shfl_xor_sync(0xffffffffu, rmax1, 2));

        const float mn0 = fmaxf(m0, rmax0);
        const float mn1 = fmaxf(m1, rmax1);
        const float alpha0 = __expf(m0 - mn0);
        const float alpha1 = __expf(m1 - mn1);
        m0 = mn0; m1 = mn1;

        float rs0 = 0.f, rs1 = 0.f;
#pragma unroll
        for (int j = 0; j < 8; j++) {
            float p0 = __expf(sacc[j][0] - mn0);
            float p1 = __expf(sacc[j][1] - mn0);
            float p2 = __expf(sacc[j][2] - mn1);
            float p3 = __expf(sacc[j][3] - mn1);
            sacc[j][0] = p0; sacc[j][1] = p1; sacc[j][2] = p2; sacc[j][3] = p3;
            rs0 += p0 + p1;
            rs1 += p2 + p3;
        }
        rs0 += __shfl_xor_sync(0xffffffffu, rs0, 1);
        rs0 += __shfl_xor_sync(0xffffffffu, rs0, 2);
        rs1 += __shfl_xor_sync(0xffffffffu, rs1, 1);
        rs1 += __shfl_xor_sync(0xffffffffu, rs1, 2);
        l0 = l0 * alpha0 + rs0;
        l1 = l1 * alpha1 + rs1;

#pragma unroll
        for (int j = 0; j < 8; j++) {
            oacc[j][0] *= alpha0; oacc[j][1] *= alpha0;
            oacc[j][2] *= alpha1; oacc[j][3] *= alpha1;
        }

        // ---- O += P @ V ----
#pragma unroll
        for (int ks = 0; ks < 4; ks++) {
            uint32_t pa[4];
            pa[0] = h2pack(sacc[2 * ks][0], sacc[2 * ks][1]);
            pa[1] = h2pack(sacc[2 * ks][2], sacc[2 * ks][3]);
            pa[2] = h2pack(sacc[2 * ks + 1][0], sacc[2 * ks + 1][1]);
            pa[3] = h2pack(sacc[2 * ks + 1][2], sacc[2 * ks + 1][3]);
#pragma unroll
            for (int p = 0; p < 4; p++) {
                uint32_t b0, b1, b2, b3;
                ldsm_x4_trans(b0, b1, b2, b3,
                              v_addr + (uint32_t)ks * (16 * QROW * 2) + (uint32_t)p * 32);
                uint32_t bf0[2] = {b0, b1}, bf1[2] = {b2, b3};
                mma_f16(oacc[2 * p], pa, bf0);
                mma_f16(oacc[2 * p + 1], pa, bf1);
            }
        }
    }

    // Epilogue: normalize, write fp32
    const float inv0 = 1.f / l0;
    const float inv1 = 1.f / l1;
    float* ob = g_o + ((size_t)(b * TX_ + q0 + warp_q)) * C_ + h * D_;
#pragma unroll
    for (int j = 0; j < 8; j++) {
        int col = 8 * j + 2 * t;
        *(float2*)&ob[(size_t)g * C_ + col] =
            make_float2(oacc[j][0] * inv0, oacc[j][1] * inv0);
        *(float2*)&ob[(size_t)(g + 8) * C_ + col] =
            make_float2(oacc[j][2] * inv1, oacc[j][3] * inv1);
    }
}

// ---------------------------------------------------------------------------
// Launch
// inputs: 0 x, 1 x_t, 2 y, 3 y_t, 4 dist, 5 min_dist, 6 Wq, 7 Wkv, 8 Wproj, 9 inv_freq
// ---------------------------------------------------------------------------
extern "C" void kernel_launch(void* const* d_in, const int* in_sizes, int n_in,
                              void* d_out, int out_size)
{
    const float* x        = (const float*)d_in[0];
    const float* x_t      = (const float*)d_in[1];
    const float* y        = (const float*)d_in[2];
    const float* y_t      = (const float*)d_in[3];
    const int*   dist     = (const int*)d_in[4];
    const int*   mind     = (const int*)d_in[5];
    const float* Wq       = (const float*)d_in[6];
    const float* Wkv      = (const float*)d_in[7];
    const float* Wproj    = (const float*)d_in[8];
    const float* inv_freq = (const float*)d_in[9];
    float* out = (float*)d_out;

    float *q_p, *k_p, *v_p, *o_p;
    cudaGetSymbolAddress((void**)&q_p, g_q);
    cudaGetSymbolAddress((void**)&k_p, g_k);
    cudaGetSymbolAddress((void**)&v_p, g_v);
    cudaGetSymbolAddress((void**)&o_p, g_o);

    // q = x @ Wq   [2048,768] x [768,768]
    gemm_tc<<<dim3(C_ / 128, (B_ * TX_) / 128), 256>>>(x, Wq, q_p, nullptr, C_, C_, 0);
    // kv = y @ Wkv [8192,768] x [768,1536] -> split into k, v
    gemm_tc<<<dim3(2 * C_ / 128, (B_ * TY_) / 128), 256>>>(y, Wkv, k_p, v_p, 2 * C_, C_, C_);
    // RoPE
    rope_kernel<<<B_ * TX_, 384>>>(q_p, x_t, inv_freq);
    rope_kernel<<<B_ * TY_, 384>>>(k_p, y_t, inv_freq);
    // banded flash attention (fp16 tensor cores)
    attn_tc<<<dim3(TX_ / 64, H_, B_), 128>>>(x_t, y_t, dist, mind);
    // final projection: out = o @ Wproj
    gemm_tc<<<dim3(C_ / 128, (B_ * TX_) / 128), 256>>>(o_p, Wproj, out, nullptr, C_, C_, 0);
}

// round 12
// speedup vs baseline: 3.4466x; 1.0663x over previous
#include <cuda_runtime.h>
#include <cuda_fp16.h>
#include <math.h>
#include <stdint.h>

// Problem constants
#define B_   2
#define TX_  1024
#define TY_  4096
#define C_   768
#define H_   12
#define D_   64

// Scratch (device globals: no allocation allowed)
__device__ __half g_qh[B_ * TX_ * C_];   // rope(q) * 0.125, fp16
__device__ __half g_kh[B_ * TY_ * C_];   // rope(k), fp16
__device__ __half g_vh[B_ * TY_ * C_];   // v, fp16
__device__ float  g_o [B_ * TX_ * C_];   // attention output, fp32

// ---------------------------------------------------------------------------
// mma / ldmatrix helpers (sm_80-era instructions, valid on base sm_103)
// ---------------------------------------------------------------------------
__device__ __forceinline__ void mma_f16(float* d, const uint32_t* a, const uint32_t* b) {
    asm volatile(
        "mma.sync.aligned.m16n8k16.row.col.f32.f16.f16.f32 "
        "{%0,%1,%2,%3}, {%4,%5,%6,%7}, {%8,%9}, {%0,%1,%2,%3};"
        : "+f"(d[0]), "+f"(d[1]), "+f"(d[2]), "+f"(d[3])
        : "r"(a[0]), "r"(a[1]), "r"(a[2]), "r"(a[3]), "r"(b[0]), "r"(b[1]));
}

__device__ __forceinline__ void ldsm_x4(uint32_t& r0, uint32_t& r1, uint32_t& r2,
                                        uint32_t& r3, uint32_t addr) {
    asm volatile("ldmatrix.sync.aligned.m8n8.x4.shared.b16 {%0,%1,%2,%3}, [%4];"
                 : "=r"(r0), "=r"(r1), "=r"(r2), "=r"(r3) : "r"(addr));
}

__device__ __forceinline__ void ldsm_x4_trans(uint32_t& r0, uint32_t& r1, uint32_t& r2,
                                              uint32_t& r3, uint32_t addr) {
    asm volatile("ldmatrix.sync.aligned.m8n8.x4.trans.shared.b16 {%0,%1,%2,%3}, [%4];"
                 : "=r"(r0), "=r"(r1), "=r"(r2), "=r"(r3) : "r"(addr));
}

__device__ __forceinline__ uint32_t h2pack(float a, float b) {
    __half2 h = __floats2half2_rn(a, b);
    return *(uint32_t*)&h;
}

// ---------------------------------------------------------------------------
// Tensor-core fp16 GEMM, fused epilogue.
// out = A[M,K] @ W[K,N], fp32 in. Block tile 128x128, 256 threads.
// mode 0: fp32 output to out0 (width N).
// mode 1: RoPE(pos) + *0.125 -> fp16 to out0 (width N). (Q path)
// mode 2: cols [0,splitN): RoPE(pos) -> fp16 out0; cols [splitN,N): fp16 out1.
// ---------------------------------------------------------------------------
#define AROW 40
#define BROW 136

__global__ __launch_bounds__(256, 1) void gemm_tc(
    const float* __restrict__ A, const float* __restrict__ W,
    void* __restrict__ out0v, void* __restrict__ out1v,
    int N, int K, int splitN, int mode,
    const float* __restrict__ pos, const float* __restrict__ invf)
{
    __shared__ __half Asm[128 * AROW];  // [m][k]
    __shared__ __half Bsm[32 * BROW];   // [k][n]
    __shared__ float spos[128];
    __shared__ float sif[32];

    const int tid = threadIdx.x;
    const int wid = tid >> 5, lane = tid & 31;
    const int g = lane >> 2, t = lane & 3;
    const int warp_m = (wid >> 1) * 32;
    const int warp_n = (wid & 1) * 64;
    const int bn = blockIdx.x * 128, bm = blockIdx.y * 128;

    if (mode != 0) {
        if (tid < 128) spos[tid] = pos[bm + tid];
        if (tid < 32) sif[tid] = invf[tid];
    }

    float acc[2][8][4];
#pragma unroll
    for (int mt = 0; mt < 2; mt++)
#pragma unroll
        for (int nt = 0; nt < 8; nt++)
#pragma unroll
            for (int e = 0; e < 4; e++) acc[mt][nt][e] = 0.f;

    const uint32_t a_base = (uint32_t)__cvta_generic_to_shared(Asm);
    const uint32_t b_base = (uint32_t)__cvta_generic_to_shared(Bsm);

    const uint32_t a_addr0 = a_base + (uint32_t)(warp_m + (lane & 15)) * (AROW * 2)
                                    + (uint32_t)(lane >> 4) * 16;
    const uint32_t a_addr1 = a_addr0 + 16 * (AROW * 2);
    const uint32_t b_addr_base = b_base + (uint32_t)(lane & 15) * (BROW * 2)
                                        + (uint32_t)(warp_n + (lane >> 4) * 8) * 2;

    const int nch = K / 32;
    for (int c = 0; c < nch; c++) {
        const int k0 = c * 32;
        __syncthreads();

#pragma unroll
        for (int i = 0; i < 4; i++) {
            int idx = tid + i * 256;
            int row = idx >> 3, c4 = (idx & 7) * 4;
            float4 v = *(const float4*)&A[(size_t)(bm + row) * K + k0 + c4];
            __half2* dst = (__half2*)&Asm[row * AROW + c4];
            dst[0] = __floats2half2_rn(v.x, v.y);
            dst[1] = __floats2half2_rn(v.z, v.w);
        }
#pragma unroll
        for (int i = 0; i < 4; i++) {
            int idx = tid + i * 256;
            int kk = idx >> 5, n4 = (idx & 31) * 4;
            float4 v = *(const float4*)&W[(size_t)(k0 + kk) * N + bn + n4];
            __half2* dst = (__half2*)&Bsm[kk * BROW + n4];
            dst[0] = __floats2half2_rn(v.x, v.y);
            dst[1] = __floats2half2_rn(v.z, v.w);
        }
        __syncthreads();

#pragma unroll
        for (int kk16 = 0; kk16 < 32; kk16 += 16) {
            uint32_t af[2][4];
            ldsm_x4(af[0][0], af[0][1], af[0][2], af[0][3], a_addr0 + kk16 * 2);
            ldsm_x4(af[1][0], af[1][1], af[1][2], af[1][3], a_addr1 + kk16 * 2);

            uint32_t bf[8][2];
#pragma unroll
            for (int p = 0; p < 4; p++) {
                ldsm_x4_trans(bf[2 * p][0], bf[2 * p][1], bf[2 * p + 1][0], bf[2 * p + 1][1],
                              b_addr_base + (uint32_t)kk16 * (BROW * 2) + (uint32_t)p * 32);
            }
#pragma unroll
            for (int nt = 0; nt < 8; nt++) {
#pragma unroll
                for (int mt = 0; mt < 2; mt++)
                    mma_f16(acc[mt][nt], af[mt], bf[nt]);
            }
        }
    }

    if (mode == 0) {
        float* dst = (float*)out0v;
#pragma unroll
        for (int mt = 0; mt < 2; mt++) {
#pragma unroll
            for (int nt = 0; nt < 8; nt++) {
                int row = bm + warp_m + mt * 16 + g;
                int col = bn + warp_n + nt * 8 + t * 2;
                *(float2*)&dst[(size_t)row * N + col] =
                    make_float2(acc[mt][nt][0], acc[mt][nt][1]);
                *(float2*)&dst[(size_t)(row + 8) * N + col] =
                    make_float2(acc[mt][nt][2], acc[mt][nt][3]);
            }
        }
    } else {
        const bool is_v = (mode == 2) && (bn >= splitN);
        __half* dsth;
        int col0, stride;
        if (mode == 1)      { dsth = (__half*)out0v; col0 = bn; stride = N; }
        else if (!is_v)     { dsth = (__half*)out0v; col0 = bn; stride = splitN; }
        else                { dsth = (__half*)out1v; col0 = bn - splitN; stride = N - splitN; }
        const float scale = (mode == 1) ? 0.125f : 1.0f;

#pragma unroll
        for (int mt = 0; mt < 2; mt++) {
            const int r0 = warp_m + mt * 16 + g;
            const float p0 = spos[r0], p1 = spos[r0 + 8];
#pragma unroll
            for (int nt = 0; nt < 8; nt++) {
                int col = col0 + warp_n + nt * 8 + t * 2;
                float e0 = acc[mt][nt][0], o0 = acc[mt][nt][1];
                float e1 = acc[mt][nt][2], o1 = acc[mt][nt][3];
                if (!is_v) {
                    const float fr = sif[(col & 63) >> 1];
                    float s, cc;
                    sincosf(p0 * fr, &s, &cc);
                    float te = e0 * cc - o0 * s, to = o0 * cc + e0 * s;
                    sincosf(p1 * fr, &s, &cc);
                    float te1 = e1 * cc - o1 * s, to1 = o1 * cc + e1 * s;
                    e0 = te * scale; o0 = to * scale;
                    e1 = te1 * scale; o1 = to1 * scale;
                }
                *(__half2*)&dsth[(size_t)(bm + r0) * stride + col] = __floats2half2_rn(e0, o0);
                *(__half2*)&dsth[(size_t)(bm + r0 + 8) * stride + col] = __floats2half2_rn(e1, o1);
            }
        }
    }
}

// ---------------------------------------------------------------------------
// Banded flash-attention, fp16 tensor cores, fp32 accumulate + softmax.
// Block = (b, h, 128-query tile), 256 threads = 8 warps, warp handles m16.
// q/k/v are pre-converted fp16 (rope + scaling fused into GEMM epilogues).
// ---------------------------------------------------------------------------
#define QROW 72   // halfs per smem row (64 + 8 pad, 144B)

__global__ __launch_bounds__(256) void attn_tc(
    const float* __restrict__ xt_g, const float* __restrict__ yt_g,
    const int* __restrict__ p_dist, const int* __restrict__ p_mind)
{
    __shared__ __align__(16) __half Qh[128 * QROW];
    __shared__ __align__(16) __half Kh[64 * QROW];
    __shared__ __align__(16) __half Vh[64 * QROW];
    __shared__ float sxt[128], syt[64];
    __shared__ int s_lo, s_hi;

    const int b = blockIdx.z, h = blockIdx.y, q0 = blockIdx.x * 128;
    const int tid = threadIdx.x;
    const int wid = tid >> 5, lane = tid & 31;
    const int g = lane >> 2, t = lane & 3;
    const int warp_q = wid * 16;

    const float fdist = (float)p_dist[0];
    const float fmind = (float)p_mind[0];
    const float* yt = yt_g + (size_t)b * TY_;

    // Q tile: 128 x 64 halves, raw copy
    const __half* qbase = g_qh + ((size_t)(b * TX_ + q0)) * C_ + h * D_;
#pragma unroll
    for (int i = 0; i < 4; i++) {
        int idx = tid + i * 256;            // 0..1023 uint4s
        int row = idx >> 3, off = (idx & 7) * 8;
        *(uint4*)&Qh[row * QROW + off] = *(const uint4*)&qbase[(size_t)row * C_ + off];
    }
    if (tid < 128) sxt[tid] = xt_g[b * TX_ + q0 + tid];

    if (tid == 0) {
        float xlo = xt_g[b * TX_ + q0] - fmind - fdist;
        float xhi = xt_g[b * TX_ + q0 + 127] - fmind;
        int lo = 0, hi = TY_;
        while (lo < hi) { int m = (lo + hi) >> 1; if (yt[m] < xlo) lo = m + 1; else hi = m; }
        s_lo = lo;
        int lo2 = lo, hi2 = TY_;
        while (lo2 < hi2) { int m = (lo2 + hi2) >> 1; if (yt[m] <= xhi) lo2 = m + 1; else hi2 = m; }
        s_hi = lo2;
    }
    __syncthreads();

    const uint32_t qb = (uint32_t)__cvta_generic_to_shared(Qh);
    const uint32_t kb = (uint32_t)__cvta_generic_to_shared(Kh);
    const uint32_t vb = (uint32_t)__cvta_generic_to_shared(Vh);

    const uint32_t a_addr = qb + (uint32_t)(warp_q + (lane & 15)) * (QROW * 2)
                               + (uint32_t)(lane >> 4) * 16;
    const uint32_t key_off = ((lane >> 4) << 3) + (lane & 7);
    const uint32_t d_off = ((lane >> 3) & 1) << 3;
    const uint32_t k_addr = kb + key_off * (QROW * 2) + d_off * 2;
    const uint32_t v_addr = vb + (uint32_t)(lane & 15) * (QROW * 2)
                               + (uint32_t)(lane >> 4) * 16;

    float oacc[8][4];
#pragma unroll
    for (int j = 0; j < 8; j++)
#pragma unroll
        for (int e = 0; e < 4; e++) oacc[j][e] = 0.f;
    float m0 = -1e30f, m1 = -1e30f, l0 = 0.f, l1 = 0.f;

    const __half* kbase = g_kh + ((size_t)b * TY_) * C_ + h * D_;
    const __half* vbase = g_vh + ((size_t)b * TY_) * C_ + h * D_;

    const int kstart = s_lo & ~63;
    const int kend = s_hi;
    const float xti0 = sxt[warp_q + g] - fmind;
    const float xti1 = sxt[warp_q + g + 8] - fmind;

    for (int k0 = kstart; k0 < kend; k0 += 64) {
        __syncthreads();   // previous tile's ldsm reads complete
        if (tid < 64) syt[tid] = yt[k0 + tid];
#pragma unroll
        for (int i = 0; i < 2; i++) {
            int idx = tid + i * 256;        // 0..511 uint4s
            int row = idx >> 3, off = (idx & 7) * 8;
            size_t go = (size_t)(k0 + row) * C_ + off;
            *(uint4*)&Kh[row * QROW + off] = *(const uint4*)&kbase[go];
            *(uint4*)&Vh[row * QROW + off] = *(const uint4*)&vbase[go];
        }
        __syncthreads();

        // ---- S = Q K^T ----
        uint32_t af[4][4];
#pragma unroll
        for (int ks = 0; ks < 4; ks++)
            ldsm_x4(af[ks][0], af[ks][1], af[ks][2], af[ks][3], a_addr + ks * 32);

        float sacc[8][4];
#pragma unroll
        for (int j = 0; j < 8; j++)
#pragma unroll
            for (int e = 0; e < 4; e++) sacc[j][e] = 0.f;

#pragma unroll
        for (int ks = 0; ks < 4; ks++) {
#pragma unroll
            for (int p = 0; p < 4; p++) {
                uint32_t b0, b1, b2, b3;
                ldsm_x4(b0, b1, b2, b3, k_addr + (uint32_t)p * (16 * QROW * 2) + (uint32_t)ks * 32);
                uint32_t bf0[2] = {b0, b1}, bf1[2] = {b2, b3};
                mma_f16(sacc[2 * p], af[ks], bf0);
                mma_f16(sacc[2 * p + 1], af[ks], bf1);
            }
        }

        // ---- mask + online softmax ----
        float rmax0 = -1e30f, rmax1 = -1e30f;
#pragma unroll
        for (int j = 0; j < 8; j++) {
            float yt0 = syt[8 * j + 2 * t];
            float yt1 = syt[8 * j + 2 * t + 1];
            sacc[j][0] = (xti0 >= yt0 && xti0 <= yt0 + fdist) ? sacc[j][0] : -1e30f;
            sacc[j][1] = (xti0 >= yt1 && xti0 <= yt1 + fdist) ? sacc[j][1] : -1e30f;
            sacc[j][2] = (xti1 >= yt0 && xti1 <= yt0 + fdist) ? sacc[j][2] : -1e30f;
            sacc[j][3] = (xti1 >= yt1 && xti1 <= yt1 + fdist) ? sacc[j][3] : -1e30f;
            rmax0 = fmaxf(rmax0, fmaxf(sacc[j][0], sacc[j][1]));
            rmax1 = fmaxf(rmax1, fmaxf(sacc[j][2], sacc[j][3]));
        }
        rmax0 = fmaxf(rmax0, __shfl_xor_sync(0xffffffffu, rmax0, 1));
        rmax0 = fmaxf(rmax0, __shfl_xor_sync(0xffffffffu, rmax0, 2));
        rmax1 = fmaxf(rmax1, __shfl_xor_sync(0xffffffffu, rmax1, 1));
        rmax1 = fmaxf(rmax1, __shfl_xor_sync(0xffffffffu, rmax1, 2));

        const float mn0 = fmaxf(m0, rmax0);
        const float mn1 = fmaxf(m1, rmax1);
        const float alpha0 = __expf(m0 - mn0);
        const float alpha1 = __expf(m1 - mn1);
        m0 = mn0; m1 = mn1;

        float rs0 = 0.f, rs1 = 0.f;
#pragma unroll
        for (int j = 0; j < 8; j++) {
            float p0 = __expf(sacc[j][0] - mn0);
            float p1 = __expf(sacc[j][1] - mn0);
            float p2 = __expf(sacc[j][2] - mn1);
            float p3 = __expf(sacc[j][3] - mn1);
            sacc[j][0] = p0; sacc[j][1] = p1; sacc[j][2] = p2; sacc[j][3] = p3;
            rs0 += p0 + p1;
            rs1 += p2 + p3;
        }
        rs0 += __shfl_xor_sync(0xffffffffu, rs0, 1);
        rs0 += __shfl_xor_sync(0xffffffffu, rs0, 2);
        rs1 += __shfl_xor_sync(0xffffffffu, rs1, 1);
        rs1 += __shfl_xor_sync(0xffffffffu, rs1, 2);
        l0 = l0 * alpha0 + rs0;
        l1 = l1 * alpha1 + rs1;

#pragma unroll
        for (int j = 0; j < 8; j++) {
            oacc[j][0] *= alpha0; oacc[j][1] *= alpha0;
            oacc[j][2] *= alpha1; oacc[j][3] *= alpha1;
        }

        // ---- O += P @ V ----
#pragma unroll
        for (int ks = 0; ks < 4; ks++) {
            uint32_t pa[4];
            pa[0] = h2pack(sacc[2 * ks][0], sacc[2 * ks][1]);
            pa[1] = h2pack(sacc[2 * ks][2], sacc[2 * ks][3]);
            pa[2] = h2pack(sacc[2 * ks + 1][0], sacc[2 * ks + 1][1]);
            pa[3] = h2pack(sacc[2 * ks + 1][2], sacc[2 * ks + 1][3]);
#pragma unroll
            for (int p = 0; p < 4; p++) {
                uint32_t b0, b1, b2, b3;
                ldsm_x4_trans(b0, b1, b2, b3,
                              v_addr + (uint32_t)ks * (16 * QROW * 2) + (uint32_t)p * 32);
                uint32_t bf0[2] = {b0, b1}, bf1[2] = {b2, b3};
                mma_f16(oacc[2 * p], pa, bf0);
                mma_f16(oacc[2 * p + 1], pa, bf1);
            }
        }
    }

    // Epilogue: normalize, write fp32
    const float inv0 = 1.f / l0;
    const float inv1 = 1.f / l1;
    float* ob = g_o + ((size_t)(b * TX_ + q0 + warp_q)) * C_ + h * D_;
#pragma unroll
    for (int j = 0; j < 8; j++) {
        int col = 8 * j + 2 * t;
        *(float2*)&ob[(size_t)g * C_ + col] =
            make_float2(oacc[j][0] * inv0, oacc[j][1] * inv0);
        *(float2*)&ob[(size_t)(g + 8) * C_ + col] =
            make_float2(oacc[j][2] * inv1, oacc[j][3] * inv1);
    }
}

// ---------------------------------------------------------------------------
// Launch
// inputs: 0 x, 1 x_t, 2 y, 3 y_t, 4 dist, 5 min_dist, 6 Wq, 7 Wkv, 8 Wproj, 9 inv_freq
// ---------------------------------------------------------------------------
extern "C" void kernel_launch(void* const* d_in, const int* in_sizes, int n_in,
                              void* d_out, int out_size)
{
    const float* x        = (const float*)d_in[0];
    const float* x_t      = (const float*)d_in[1];
    const float* y        = (const float*)d_in[2];
    const float* y_t      = (const float*)d_in[3];
    const int*   dist     = (const int*)d_in[4];
    const int*   mind     = (const int*)d_in[5];
    const float* Wq       = (const float*)d_in[6];
    const float* Wkv      = (const float*)d_in[7];
    const float* Wproj    = (const float*)d_in[8];
    const float* inv_freq = (const float*)d_in[9];
    float* out = (float*)d_out;

    __half *qh_p, *kh_p, *vh_p;
    float *o_p;
    cudaGetSymbolAddress((void**)&qh_p, g_qh);
    cudaGetSymbolAddress((void**)&kh_p, g_kh);
    cudaGetSymbolAddress((void**)&vh_p, g_vh);
    cudaGetSymbolAddress((void**)&o_p, g_o);

    // q = rope(x @ Wq) * 0.125 -> fp16
    gemm_tc<<<dim3(C_ / 128, (B_ * TX_) / 128), 256>>>(
        x, Wq, qh_p, nullptr, C_, C_, 0, 1, x_t, inv_freq);
    // kv = y @ Wkv; k = rope(kv[:,:768]) -> fp16, v = kv[:,768:] -> fp16
    gemm_tc<<<dim3(2 * C_ / 128, (B_ * TY_) / 128), 256>>>(
        y, Wkv, kh_p, vh_p, 2 * C_, C_, C_, 2, y_t, inv_freq);
    // banded flash attention (fp16 tensor cores, 128-query tiles)
    attn_tc<<<dim3(TX_ / 128, H_, B_), 256>>>(x_t, y_t, dist, mind);
    // final projection: out = o @ Wproj (fp32 out)
    gemm_tc<<<dim3(C_ / 128, (B_ * TX_) / 128), 256>>>(
        o_p, Wproj, out, nullptr, C_, C_, 0, 0, nullptr, nullptr);
}